// round 12
// baseline (speedup 1.0000x reference)
#include <cuda_runtime.h>

// Blobber fused single pass (reference's 4 iterations are identical — each
// re-convolves `inputs`). out = sig2(box3(sig1(box3(in)))).
// Warp-streaming, float4/lane: 32 lanes cover 128 aligned cols; lanes 1..30
// store 120 output cols, lanes 0/31 are halo. tanh.approx sigmoid.
// SEG=16 row segments for occupancy. No smem, no barriers.

#define IMG     512
#define STRIPW  120          // output cols per warp
#define NSTRIP  5            // 5*120 = 600 >= 512 (tail lanes predicated off)
#define SEG     16
#define NWARPS  4            // 128-thread CTAs

// sigma((s/9 - b)*1000) = 0.5 + 0.5*tanh(s*(500/9) - 500b)
#define STCL (500.0f / 9.0f)
#define C1T  (-5.0f)         // b = 0.01
#define C2T  (-450.0f)       // b = 0.9

__device__ __forceinline__ float sigt(float s, float cc) {
    float t = fmaf(s, STCL, cc);
    float th; asm("tanh.approx.f32 %0, %1;" : "=f"(th) : "f"(t));
    return fmaf(th, 0.5f, 0.5f);
}

struct Roll4 { float4 h1a, h1b, h2a, h2b; };

__device__ __forceinline__ float4 zero4() { return make_float4(0.f, 0.f, 0.f, 0.f); }

template<bool CHECK>
__device__ __forceinline__ float4 ld4(const float* p, bool colv) {
    if (CHECK) {
        float4 v = zero4();
        if (colv) v = *(const float4*)p;
        return v;
    }
    return *(const float4*)p;
}

// one pipeline step over 4 columns; rows statically valid
template<bool STORE, bool CHECK>
__device__ __forceinline__ void step4(float4 v, Roll4& R, bool colv, bool outok,
                                      float* st) {
    float vup = __shfl_up_sync(0xffffffffu, v.w, 1);    // col c-1
    float vdn = __shfl_down_sync(0xffffffffu, v.x, 1);  // col c+4
    float t1 = v.x + v.y, t2 = v.z + v.w;
    float4 h1 = make_float4(vup + t1, t1 + v.z, v.y + t2, t2 + vdn);
    float4 s1 = make_float4(R.h1a.x + R.h1b.x + h1.x,
                            R.h1a.y + R.h1b.y + h1.y,
                            R.h1a.z + R.h1b.z + h1.z,
                            R.h1a.w + R.h1b.w + h1.w);
    R.h1a = R.h1b; R.h1b = h1;
    float4 mid;
    if (CHECK) {            // mid must be exact 0 outside the image
        mid.x = colv ? sigt(s1.x, C1T) : 0.0f;
        mid.y = colv ? sigt(s1.y, C1T) : 0.0f;
        mid.z = colv ? sigt(s1.z, C1T) : 0.0f;
        mid.w = colv ? sigt(s1.w, C1T) : 0.0f;
    } else {
        mid.x = sigt(s1.x, C1T); mid.y = sigt(s1.y, C1T);
        mid.z = sigt(s1.z, C1T); mid.w = sigt(s1.w, C1T);
    }
    float mup = __shfl_up_sync(0xffffffffu, mid.w, 1);
    float mdn = __shfl_down_sync(0xffffffffu, mid.x, 1);
    float m1 = mid.x + mid.y, m2 = mid.z + mid.w;
    float4 h2 = make_float4(mup + m1, m1 + mid.z, mid.y + m2, m2 + mdn);
    float4 s2 = make_float4(R.h2a.x + R.h2b.x + h2.x,
                            R.h2a.y + R.h2b.y + h2.y,
                            R.h2a.z + R.h2b.z + h2.z,
                            R.h2a.w + R.h2b.w + h2.w);
    R.h2a = R.h2b; R.h2b = h2;
    if (STORE && outok) {
        float4 r = make_float4(sigt(s2.x, C2T), sigt(s2.y, C2T),
                               sigt(s2.z, C2T), sigt(s2.w, C2T));
        *(float4*)st = r;
    }
}

// interior-row segment (rows S-2..S+17 statically in-image), batches of 2
template<bool CHECK>
__device__ __forceinline__ void fast_seg(const float* ip, float* op,
                                         bool colv, bool outok) {
    Roll4 R; R.h1a = zero4(); R.h1b = zero4(); R.h2a = zero4(); R.h2b = zero4();

    float4 b0 = ld4<CHECK>(ip, colv);
    float4 b1 = ld4<CHECK>(ip + IMG, colv);
    ip += 2 * IMG;

    // warm-up: 2 batches (4 steps, g = S-2..S+1, no stores)
    #pragma unroll
    for (int w = 0; w < 2; w++) {
        float4 n0 = ld4<CHECK>(ip, colv);
        float4 n1 = ld4<CHECK>(ip + IMG, colv);
        ip += 2 * IMG;
        step4<false, CHECK>(b0, R, colv, outok, op);
        step4<false, CHECK>(b1, R, colv, outok, op);
        b0 = n0; b1 = n1;
    }
    // 7 storing batches with prefetch
    #pragma unroll 1
    for (int k = 0; k < 7; k++) {
        float4 n0 = ld4<CHECK>(ip, colv);
        float4 n1 = ld4<CHECK>(ip + IMG, colv);
        ip += 2 * IMG;
        step4<true, CHECK>(b0, R, colv, outok, op);
        step4<true, CHECK>(b1, R, colv, outok, op + IMG);
        op += 2 * IMG;
        b0 = n0; b1 = n1;
    }
    // drain batch
    step4<true, CHECK>(b0, R, colv, outok, op);
    step4<true, CHECK>(b1, R, colv, outok, op + IMG);
}

// guarded step for boundary-row segments
__device__ __forceinline__ void stepG4(int g, float4 v, int S, Roll4& R,
                                       bool colv, bool outok,
                                       float* __restrict__ oimg, int c) {
    float vup = __shfl_up_sync(0xffffffffu, v.w, 1);
    float vdn = __shfl_down_sync(0xffffffffu, v.x, 1);
    float t1 = v.x + v.y, t2 = v.z + v.w;
    float4 h1 = make_float4(vup + t1, t1 + v.z, v.y + t2, t2 + vdn);
    float4 s1 = make_float4(R.h1a.x + R.h1b.x + h1.x,
                            R.h1a.y + R.h1b.y + h1.y,
                            R.h1a.z + R.h1b.z + h1.z,
                            R.h1a.w + R.h1b.w + h1.w);
    R.h1a = R.h1b; R.h1b = h1;
    float4 mid = zero4();
    int m = g - 1;                 // exact 0 outside the image
    if ((unsigned)m < (unsigned)IMG && colv) {
        mid.x = sigt(s1.x, C1T); mid.y = sigt(s1.y, C1T);
        mid.z = sigt(s1.z, C1T); mid.w = sigt(s1.w, C1T);
    }
    float mup = __shfl_up_sync(0xffffffffu, mid.w, 1);
    float mdn = __shfl_down_sync(0xffffffffu, mid.x, 1);
    float m1 = mid.x + mid.y, m2 = mid.z + mid.w;
    float4 h2 = make_float4(mup + m1, m1 + mid.z, mid.y + m2, m2 + mdn);
    float4 s2 = make_float4(R.h2a.x + R.h2b.x + h2.x,
                            R.h2a.y + R.h2b.y + h2.y,
                            R.h2a.z + R.h2b.z + h2.z,
                            R.h2a.w + R.h2b.w + h2.w);
    R.h2a = R.h2b; R.h2b = h2;
    int o = g - 2;
    if (o >= S && o < IMG && outok) {
        float4 r = make_float4(sigt(s2.x, C2T), sigt(s2.y, C2T),
                               sigt(s2.z, C2T), sigt(s2.w, C2T));
        *(float4*)(oimg + (size_t)o * IMG + c) = r;
    }
}

__global__ __launch_bounds__(32 * NWARPS, 8)
void blobber_ws5(const float* __restrict__ in, float* __restrict__ out) {
    const int lane = threadIdx.x & 31;
    const int wid  = threadIdx.x >> 5;

    const int  strip0 = blockIdx.x * STRIPW;
    const int  c      = strip0 + 4 * lane - 4;        // 4-aligned lane base
    const bool colv   = (unsigned)c < (unsigned)IMG;  // whole quad in/out (512%4==0)
    const bool outok  = ((unsigned)(lane - 1) < 30u) && colv;

    const float* img  = in  + (size_t)blockIdx.z * IMG * IMG;
    float*       oimg = out + (size_t)blockIdx.z * IMG * IMG;

    const int S = (blockIdx.y * NWARPS + wid) * SEG;  // output rows [S, S+16)

    if (S >= 2 && S + 17 < IMG) {
        const float* ip = img + (size_t)(S - 2) * IMG + c;
        float*       op = oimg + (size_t)S * IMG + c;
        if (blockIdx.x > 0 && blockIdx.x < NSTRIP - 1)
            fast_seg<false>(ip, op, colv, outok);
        else
            fast_seg<true>(ip, op, colv, outok);
    } else {
        // boundary rows: S == 0 or S == 496
        Roll4 R; R.h1a = zero4(); R.h1b = zero4(); R.h2a = zero4(); R.h2b = zero4();
        #define LDG_ROW4(g) ((colv && (unsigned)(g) < (unsigned)IMG) \
            ? *(const float4*)(img + (size_t)(g) * IMG + c) : zero4())
        float4 vb0 = LDG_ROW4(S - 2), vb1 = LDG_ROW4(S - 1);
        #pragma unroll 1
        for (int g = S - 2; g < S + SEG + 2; g += 2) {
            float4 n0 = zero4(), n1 = zero4();
            if (g + 2 < S + SEG + 2) { n0 = LDG_ROW4(g + 2); n1 = LDG_ROW4(g + 3); }
            stepG4(g + 0, vb0, S, R, colv, outok, oimg, c);
            stepG4(g + 1, vb1, S, R, colv, outok, oimg, c);
            vb0 = n0; vb1 = n1;
        }
        #undef LDG_ROW4
    }
}

extern "C" void kernel_launch(void* const* d_in, const int* in_sizes, int n_in,
                              void* d_out, int out_size) {
    const float* in = (const float*)d_in[0];
    float* out = (float*)d_out;
    dim3 grid(NSTRIP, IMG / (SEG * NWARPS), 32);   // (5, 8, 32) = 1280 CTAs
    blobber_ws5<<<grid, 32 * NWARPS>>>(in, out);
}

// round 13
// speedup vs baseline: 1.0190x; 1.0190x over previous
#include <cuda_runtime.h>

// Blobber fused single pass (reference's 4 iterations are identical — each
// re-convolves `inputs`). out = sig2(box3(sig1(box3(in)))).
// Warp-streaming float4/lane. NO mid-shuffle: each lane computes 6 redundant
// mid values (cols c-1..c+4) from inputs c-2..c+5 fetched with 4 independent
// up-front shuffles. Critical path = 1 shuffle wave + adds + 2 tanh waves.
// tanh.approx sigmoid. SEG=16 segments. No smem, no barriers.

#define IMG     512
#define STRIPW  120          // output cols per warp (lanes 1..30 store 4 each)
#define NSTRIP  5            // 5*120 = 600 >= 512
#define SEG     16
#define NWARPS  4            // 128-thread CTAs

// sigma((s/9 - b)*1000) = 0.5 + 0.5*tanh(s*(500/9) - 500b)
#define STCL (500.0f / 9.0f)
#define C1T  (-5.0f)         // b = 0.01
#define C2T  (-450.0f)       // b = 0.9

__device__ __forceinline__ float sigt(float s, float cc) {
    float t = fmaf(s, STCL, cc);
    float th; asm("tanh.approx.f32 %0, %1;" : "=f"(th) : "f"(t));
    return fmaf(th, 0.5f, 0.5f);
}

struct Roll {
    float r1a[6], r1b[6];   // h1 rolling window (cols c-1..c+4)
    float r2a[4], r2b[4];   // h2 rolling window (cols c..c+3)
};

__device__ __forceinline__ float4 zero4() { return make_float4(0.f,0.f,0.f,0.f); }

template<bool CHECK>
__device__ __forceinline__ float4 ld4(const float* p, bool colv) {
    if (CHECK) { float4 v = zero4(); if (colv) v = *(const float4*)p; return v; }
    return *(const float4*)p;
}

// One pipeline step over this lane's 4 output columns. mv = 6 mid-column
// 0/1 masks (CHECK tier only). Rows statically valid.
template<bool STORE, bool CHECK>
__device__ __forceinline__ void step4(float4 v, Roll& R, const float* mv,
                                      bool outok, float* st) {
    // 4 independent shuffles: inputs c-2, c-1 (lane-1), c+4, c+5 (lane+1)
    float am2 = __shfl_up_sync  (0xffffffffu, v.z, 1);
    float am1 = __shfl_up_sync  (0xffffffffu, v.w, 1);
    float ap4 = __shfl_down_sync(0xffffffffu, v.x, 1);
    float ap5 = __shfl_down_sync(0xffffffffu, v.y, 1);

    // h1 at cols c-1 .. c+4
    float p0 = am2 + am1, p1 = v.x + v.y, p2 = v.z + v.w, p3 = ap4 + ap5;
    float h1[6];
    h1[0] = p0 + v.x;   // c-1
    h1[1] = am1 + p1;   // c
    h1[2] = p1 + v.z;   // c+1
    h1[3] = v.y + p2;   // c+2
    h1[4] = p2 + ap4;   // c+3
    h1[5] = v.w + p3;   // c+4

    // vertical 3-sum + sigmoid -> 6 mids (row m = g-1)
    float mid[6];
    #pragma unroll
    for (int j = 0; j < 6; j++) {
        float s1 = R.r1a[j] + R.r1b[j] + h1[j];
        R.r1a[j] = R.r1b[j]; R.r1b[j] = h1[j];
        float mj = sigt(s1, C1T);
        mid[j] = CHECK ? mj * mv[j] : mj;   // exact 0 outside image
    }

    // h2 at cols c .. c+3 (no shuffle needed)
    float q0 = mid[0] + mid[1], q1 = mid[2] + mid[3], q2 = mid[4] + mid[5];
    float h2[4];
    h2[0] = q0 + mid[2];
    h2[1] = mid[1] + q1;
    h2[2] = q1 + mid[4];
    h2[3] = mid[3] + q2;

    float s2[4];
    #pragma unroll
    for (int j = 0; j < 4; j++) {
        s2[j] = R.r2a[j] + R.r2b[j] + h2[j];
        R.r2a[j] = R.r2b[j]; R.r2b[j] = h2[j];
    }
    if (STORE && outok) {
        float4 r = make_float4(sigt(s2[0], C2T), sigt(s2[1], C2T),
                               sigt(s2[2], C2T), sigt(s2[3], C2T));
        *(float4*)st = r;
    }
}

template<bool CHECK>
__device__ __forceinline__ void fast_seg(const float* ip, float* op,
                                         const float* mv, bool colv, bool outok) {
    Roll R;
    #pragma unroll
    for (int j = 0; j < 6; j++) { R.r1a[j] = 0.f; R.r1b[j] = 0.f; }
    #pragma unroll
    for (int j = 0; j < 4; j++) { R.r2a[j] = 0.f; R.r2b[j] = 0.f; }

    float4 b0 = ld4<CHECK>(ip, colv);
    float4 b1 = ld4<CHECK>(ip + IMG, colv);
    ip += 2 * IMG;

    // warm-up: rows S-2 .. S+1 (no stores)
    #pragma unroll
    for (int w = 0; w < 2; w++) {
        float4 n0 = ld4<CHECK>(ip, colv);
        float4 n1 = ld4<CHECK>(ip + IMG, colv);
        ip += 2 * IMG;
        step4<false, CHECK>(b0, R, mv, outok, op);
        step4<false, CHECK>(b1, R, mv, outok, op);
        b0 = n0; b1 = n1;
    }
    // 7 storing batches with prefetch
    #pragma unroll 1
    for (int k = 0; k < 7; k++) {
        float4 n0 = ld4<CHECK>(ip, colv);
        float4 n1 = ld4<CHECK>(ip + IMG, colv);
        ip += 2 * IMG;
        step4<true, CHECK>(b0, R, mv, outok, op);
        step4<true, CHECK>(b1, R, mv, outok, op + IMG);
        op += 2 * IMG;
        b0 = n0; b1 = n1;
    }
    // drain
    step4<true, CHECK>(b0, R, mv, outok, op);
    step4<true, CHECK>(b1, R, mv, outok, op + IMG);
}

// guarded step for boundary-row segments (adds row checks)
__device__ __forceinline__ void stepB(int g, float4 v, int S, Roll& R,
                                      const float* mv, bool outok,
                                      float* __restrict__ oimg, int c) {
    float am2 = __shfl_up_sync  (0xffffffffu, v.z, 1);
    float am1 = __shfl_up_sync  (0xffffffffu, v.w, 1);
    float ap4 = __shfl_down_sync(0xffffffffu, v.x, 1);
    float ap5 = __shfl_down_sync(0xffffffffu, v.y, 1);
    float p0 = am2 + am1, p1 = v.x + v.y, p2 = v.z + v.w, p3 = ap4 + ap5;
    float h1[6] = { p0 + v.x, am1 + p1, p1 + v.z, v.y + p2, p2 + ap4, v.w + p3 };
    const float rowm = ((unsigned)(g - 1) < (unsigned)IMG) ? 1.0f : 0.0f;
    float mid[6];
    #pragma unroll
    for (int j = 0; j < 6; j++) {
        float s1 = R.r1a[j] + R.r1b[j] + h1[j];
        R.r1a[j] = R.r1b[j]; R.r1b[j] = h1[j];
        mid[j] = sigt(s1, C1T) * mv[j] * rowm;   // exact 0 outside image
    }
    float q0 = mid[0] + mid[1], q1 = mid[2] + mid[3], q2 = mid[4] + mid[5];
    float h2[4] = { q0 + mid[2], mid[1] + q1, q1 + mid[4], mid[3] + q2 };
    float s2[4];
    #pragma unroll
    for (int j = 0; j < 4; j++) {
        s2[j] = R.r2a[j] + R.r2b[j] + h2[j];
        R.r2a[j] = R.r2b[j]; R.r2b[j] = h2[j];
    }
    int o = g - 2;
    if (o >= S && o < IMG && outok) {
        float4 r = make_float4(sigt(s2[0], C2T), sigt(s2[1], C2T),
                               sigt(s2[2], C2T), sigt(s2[3], C2T));
        *(float4*)(oimg + (size_t)o * IMG + c) = r;
    }
}

__global__ __launch_bounds__(32 * NWARPS, 8)
void blobber_ws6(const float* __restrict__ in, float* __restrict__ out) {
    const int lane = threadIdx.x & 31;
    const int wid  = threadIdx.x >> 5;

    const int  strip0 = blockIdx.x * STRIPW;
    const int  c      = strip0 + 4 * lane - 4;        // 4-aligned lane base
    const bool colv   = (unsigned)c < (unsigned)IMG;  // quad fully in/out
    const bool outok  = ((unsigned)(lane - 1) < 30u) && colv;

    // 6 mid-column validity masks (cols c-1 .. c+4); loop-invariant
    float mv[6];
    #pragma unroll
    for (int j = 0; j < 6; j++)
        mv[j] = ((unsigned)(c - 1 + j) < (unsigned)IMG) ? 1.0f : 0.0f;

    const float* img  = in  + (size_t)blockIdx.z * IMG * IMG;
    float*       oimg = out + (size_t)blockIdx.z * IMG * IMG;

    const int S = (blockIdx.y * NWARPS + wid) * SEG;  // output rows [S, S+16)

    if (S >= 2 && S + 17 < IMG) {
        const float* ip = img + (size_t)(S - 2) * IMG + c;
        float*       op = oimg + (size_t)S * IMG + c;
        if (blockIdx.x > 0 && blockIdx.x < NSTRIP - 1)
            fast_seg<false>(ip, op, mv, colv, outok);
        else
            fast_seg<true>(ip, op, mv, colv, outok);
    } else {
        // boundary rows: S == 0 or S == 496
        Roll R;
        #pragma unroll
        for (int j = 0; j < 6; j++) { R.r1a[j] = 0.f; R.r1b[j] = 0.f; }
        #pragma unroll
        for (int j = 0; j < 4; j++) { R.r2a[j] = 0.f; R.r2b[j] = 0.f; }
        #define LDG_ROW4(g) ((colv && (unsigned)(g) < (unsigned)IMG) \
            ? *(const float4*)(img + (size_t)(g) * IMG + c) : zero4())
        float4 vb0 = LDG_ROW4(S - 2), vb1 = LDG_ROW4(S - 1);
        #pragma unroll 1
        for (int g = S - 2; g < S + SEG + 2; g += 2) {
            float4 n0 = zero4(), n1 = zero4();
            if (g + 2 < S + SEG + 2) { n0 = LDG_ROW4(g + 2); n1 = LDG_ROW4(g + 3); }
            stepB(g + 0, vb0, S, R, mv, outok, oimg, c);
            stepB(g + 1, vb1, S, R, mv, outok, oimg, c);
            vb0 = n0; vb1 = n1;
        }
        #undef LDG_ROW4
    }
}

extern "C" void kernel_launch(void* const* d_in, const int* in_sizes, int n_in,
                              void* d_out, int out_size) {
    const float* in = (const float*)d_in[0];
    float* out = (float*)d_out;
    dim3 grid(NSTRIP, IMG / (SEG * NWARPS), 32);   // (5, 8, 32) = 1280 CTAs
    blobber_ws6<<<grid, 32 * NWARPS>>>(in, out);
}